// round 1
// baseline (speedup 1.0000x reference)
#include <cuda_runtime.h>
#include <math.h>

#define NN 50000
#define EE 1600000
#define HIN 7
#define HH 128
#define FCC 256
#define CC 2
#define GG 512

// ---------------- scratch (device globals; no allocation in launch) ----------
__device__ float g_h [NN*HH];   // current node features (layer output)
__device__ float g_xl[NN*HH];   // source-transformed features
__device__ float g_xr[NN*HH];   // target-transformed features
__device__ float g_e [EE];      // per-edge attention logits scratch
__device__ int   g_off[NN+1];   // CSR offsets (by dst)
__device__ int   g_cur[NN];     // degree counts / scatter cursors
__device__ int   g_csrc[EE];    // CSR src indices
__device__ float g_pool[GG*HH]; // pooled sums
__device__ int   g_cnt[GG];     // nodes per graph

__device__ __forceinline__ float lrelu02(float x){ return x > 0.f ? x : 0.2f*x; }
__device__ __forceinline__ float eluf(float x){ return x > 0.f ? x : (__expf(x) - 1.f); }

// ---------------- CSR build --------------------------------------------------
__global__ void k_init() {
    int i = blockIdx.x*blockDim.x + threadIdx.x;
    if (i < NN)    g_cur[i]  = 0;
    if (i < GG*HH) g_pool[i] = 0.f;
    if (i < GG)    g_cnt[i]  = 0;
}

__global__ void k_hist(const int* __restrict__ ei) {
    int i = blockIdx.x*blockDim.x + threadIdx.x;
    if (i < EE) atomicAdd(&g_cur[ei[EE + i]], 1);
}

__global__ void k_scan() {
    __shared__ int sums[1024];
    const int t = threadIdx.x;
    const int PER = (NN + 1023) / 1024;   // 49
    int base = t * PER;
    int local = 0;
    for (int k = 0; k < PER; k++) { int i = base + k; if (i < NN) local += g_cur[i]; }
    sums[t] = local; __syncthreads();
    for (int d = 1; d < 1024; d <<= 1) {
        int v = (t >= d) ? sums[t - d] : 0;
        __syncthreads();
        sums[t] += v;
        __syncthreads();
    }
    int prefix = (t == 0) ? 0 : sums[t - 1];
    for (int k = 0; k < PER; k++) {
        int i = base + k;
        if (i < NN) { int d = g_cur[i]; g_off[i] = prefix; prefix += d; }
    }
    if (t == 1023) g_off[NN] = prefix;
}

__global__ void k_setcur() {
    int i = blockIdx.x*blockDim.x + threadIdx.x;
    if (i < NN) g_cur[i] = g_off[i];
}

__global__ void k_scatter(const int* __restrict__ ei) {
    int i = blockIdx.x*blockDim.x + threadIdx.x;
    if (i >= EE) return;
    int s = ei[i];
    int d = ei[EE + i];
    int pos = atomicAdd(&g_cur[d], 1);
    g_csrc[pos] = s;
}

// ---------------- layer 0 linear (K=7) ---------------------------------------
__global__ __launch_bounds__(128) void k_lin0(const float* __restrict__ x,
                                              const float* __restrict__ Wl, const float* __restrict__ bl,
                                              const float* __restrict__ Wr, const float* __restrict__ br) {
    __shared__ float xs[32*HIN];
    const int t = threadIdx.x;                // output column 0..127
    const int n0 = blockIdx.x * 32;
    for (int i = t; i < 32*HIN; i += 128) {
        int n = n0 + i / HIN;
        xs[i] = (n < NN) ? x[n*HIN + (i % HIN)] : 0.f;
    }
    __syncthreads();
    float wl[HIN], wr[HIN];
#pragma unroll
    for (int k = 0; k < HIN; k++) { wl[k] = Wl[k*HH + t]; wr[k] = Wr[k*HH + t]; }
    float blv = bl[t], brv = br[t];
    for (int nn = 0; nn < 32; nn++) {
        int n = n0 + nn;
        if (n >= NN) break;
        float al = blv, ar = brv;
#pragma unroll
        for (int k = 0; k < HIN; k++) {
            float xv = xs[nn*HIN + k];
            al += xv * wl[k];
            ar += xv * wr[k];
        }
        g_xl[n*HH + t] = al;
        g_xr[n*HH + t] = ar;
    }
}

// ---------------- dual linear (K=128): xl = h@Wl+bl ; xr = h@Wr+br -----------
// block: 32 rows x 256 cols (128 xl || 128 xr), 256 threads, 4x8 micro-tile
__global__ __launch_bounds__(256) void k_lin(const float* __restrict__ Wl, const float* __restrict__ bl,
                                             const float* __restrict__ Wr, const float* __restrict__ br) {
    __shared__ float As[32][68];     // [k][row], padded
    __shared__ float Ws[32*256];     // [k][col]
    const int t   = threadIdx.x;
    const int row0 = blockIdx.x * 32;
    const int tc = t & 31;           // 0..31
    const int tr = t >> 5;           // 0..7 -> rows 4*tr..4*tr+3
    float acc[4][8];
#pragma unroll
    for (int i = 0; i < 4; i++)
#pragma unroll
        for (int j = 0; j < 8; j++) acc[i][j] = 0.f;

    for (int kt = 0; kt < HH; kt += 32) {
        {   // A tile: 32 rows x 32 k, stored transposed
            int r  = t >> 3;          // 0..31
            int kq = t & 7;           // 0..7 -> k = 4*kq..4*kq+3
            int row = row0 + r;
            float4 v = make_float4(0.f, 0.f, 0.f, 0.f);
            if (row < NN) v = *(const float4*)(g_h + row*HH + kt + kq*4);
            As[kq*4+0][r] = v.x; As[kq*4+1][r] = v.y;
            As[kq*4+2][r] = v.z; As[kq*4+3][r] = v.w;
        }
#pragma unroll
        for (int q = 0; q < 8; q++) {  // W tile: 32 k x 256 cols
            int s  = t + 256*q;        // 0..2047 float4 slots
            int k  = s >> 6;
            int c4 = (s & 63) * 4;
            const float* src = (c4 < HH) ? (Wl + (kt + k)*HH + c4)
                                         : (Wr + (kt + k)*HH + (c4 - HH));
            *(float4*)(Ws + k*256 + c4) = *(const float4*)src;
        }
        __syncthreads();
#pragma unroll
        for (int k = 0; k < 32; k++) {
            float a0 = As[k][4*tr+0], a1 = As[k][4*tr+1];
            float a2 = As[k][4*tr+2], a3 = As[k][4*tr+3];
#pragma unroll
            for (int j = 0; j < 8; j++) {
                float b = Ws[k*256 + tc + 32*j];
                acc[0][j] += a0*b; acc[1][j] += a1*b;
                acc[2][j] += a2*b; acc[3][j] += a3*b;
            }
        }
        __syncthreads();
    }
#pragma unroll
    for (int i = 0; i < 4; i++) {
        int row = row0 + 4*tr + i;
        if (row >= NN) continue;
#pragma unroll
        for (int j = 0; j < 8; j++) {
            int c = tc + 32*j;
            if (c < HH) g_xl[row*HH + c]        = acc[i][j] + bl[c];
            else        g_xr[row*HH + (c - HH)] = acc[i][j] + br[c - HH];
        }
    }
}

// ---------------- fused edge attention + softmax + aggregate -----------------
// one warp per destination node; self-loop handled in registers
__global__ __launch_bounds__(256) void k_edge(const float* __restrict__ att,
                                              const float* __restrict__ bo) {
    const int gw   = (blockIdx.x * 256 + threadIdx.x) >> 5;
    const int lane = threadIdx.x & 31;
    if (gw >= NN) return;
    const int dst = gw;

    const float4* __restrict__ xlv = (const float4*)g_xl;
    const float4* __restrict__ xrv = (const float4*)g_xr;

    float4 a4  = *(const float4*)(att + lane*4);
    float4 xr4 = xrv[dst*32 + lane];
    float4 xd4 = xlv[dst*32 + lane];   // xl[dst] for self-loop

    // self-loop logit
    float p = a4.x*lrelu02(xd4.x + xr4.x) + a4.y*lrelu02(xd4.y + xr4.y)
            + a4.z*lrelu02(xd4.z + xr4.z) + a4.w*lrelu02(xd4.w + xr4.w);
#pragma unroll
    for (int o = 16; o > 0; o >>= 1) p += __shfl_xor_sync(0xffffffffu, p, o);
    const float eself = p;

    float m = eself, s = 1.0f;   // online softmax state
    const int beg = g_off[dst], end = g_off[dst + 1];

    for (int j = beg; j < end; j++) {
        int sn = g_csrc[j];
        float4 v = xlv[sn*32 + lane];
        float q = a4.x*lrelu02(v.x + xr4.x) + a4.y*lrelu02(v.y + xr4.y)
                + a4.z*lrelu02(v.z + xr4.z) + a4.w*lrelu02(v.w + xr4.w);
#pragma unroll
        for (int o = 16; o > 0; o >>= 1) q += __shfl_xor_sync(0xffffffffu, q, o);
        if (lane == 0) g_e[j] = q;
        if (q > m) { s = s*__expf(m - q) + 1.0f; m = q; }
        else       { s += __expf(q - m); }
    }

    const float inv = 1.0f / s;
    float w0 = __expf(eself - m) * inv;
    float4 acc;
    acc.x = w0*xd4.x; acc.y = w0*xd4.y; acc.z = w0*xd4.z; acc.w = w0*xd4.w;

    for (int j = beg; j < end; j++) {
        int sn  = g_csrc[j];
        float w = __expf(g_e[j] - m) * inv;
        float4 v = xlv[sn*32 + lane];
        acc.x += w*v.x; acc.y += w*v.y; acc.z += w*v.z; acc.w += w*v.w;
    }

    float4 b4 = *(const float4*)(bo + lane*4);
    float4 o;
    o.x = eluf(acc.x + b4.x); o.y = eluf(acc.y + b4.y);
    o.z = eluf(acc.z + b4.z); o.w = eluf(acc.w + b4.w);
    ((float4*)g_h)[dst*32 + lane] = o;
}

// ---------------- global mean pool (atomic sums) ------------------------------
__global__ void k_pool(const int* __restrict__ batch) {
    int id = blockIdx.x*blockDim.x + threadIdx.x;
    int node = id >> 5, lane = id & 31;
    if (node >= NN) return;
    int g = batch[node];
    float4 v = ((const float4*)g_h)[node*32 + lane];
    atomicAdd(&g_pool[g*HH + lane*4 + 0], v.x);
    atomicAdd(&g_pool[g*HH + lane*4 + 1], v.y);
    atomicAdd(&g_pool[g*HH + lane*4 + 2], v.z);
    atomicAdd(&g_pool[g*HH + lane*4 + 3], v.w);
    if (lane == 0) atomicAdd(&g_cnt[g], 1);
}

// ---------------- MLP head + log_softmax -------------------------------------
__global__ __launch_bounds__(128) void k_head(const float* __restrict__ fc1W, const float* __restrict__ fc1b,
                                              const float* __restrict__ fc2W, const float* __restrict__ fc2b,
                                              float* __restrict__ out) {
    __shared__ float gs[HH];
    __shared__ float red0[128], red1[128];
    const int gid = blockIdx.x;
    const int t = threadIdx.x;
    float c = (float)g_cnt[gid];
    if (c < 1.f) c = 1.f;
    gs[t] = g_pool[gid*HH + t] / c;
    __syncthreads();
    float p0 = 0.f, p1 = 0.f;
    for (int cc = t; cc < FCC; cc += 128) {
        float z = fc1b[cc];
        for (int k = 0; k < HH; k++) z += gs[k] * fc1W[k*FCC + cc];
        z = fmaxf(z, 0.f);
        p0 += z * fc2W[cc*CC + 0];
        p1 += z * fc2W[cc*CC + 1];
    }
    red0[t] = p0; red1[t] = p1;
    __syncthreads();
    for (int st = 64; st > 0; st >>= 1) {
        if (t < st) { red0[t] += red0[t + st]; red1[t] += red1[t + st]; }
        __syncthreads();
    }
    if (t == 0) {
        float l0 = red0[0] + fc2b[0];
        float l1 = red1[0] + fc2b[1];
        float mm  = fmaxf(l0, l1);
        float lse = mm + logf(__expf(l0 - mm) + __expf(l1 - mm));
        out[gid*CC + 0] = l0 - lse;
        out[gid*CC + 1] = l1 - lse;
    }
}

// ---------------- launch ------------------------------------------------------
extern "C" void kernel_launch(void* const* d_in, const int* in_sizes, int n_in,
                              void* d_out, int out_size) {
    const float* x     = (const float*)d_in[0];
    const int*   ei    = (const int*)  d_in[1];
    const int*   batch = (const int*)  d_in[2];
    const float* Wl0 = (const float*)d_in[3];  const float* bl0 = (const float*)d_in[4];
    const float* Wr0 = (const float*)d_in[5];  const float* br0 = (const float*)d_in[6];
    const float* at0 = (const float*)d_in[7];  const float* bo0 = (const float*)d_in[8];
    const float* Wl1 = (const float*)d_in[9];  const float* bl1 = (const float*)d_in[10];
    const float* Wr1 = (const float*)d_in[11]; const float* br1 = (const float*)d_in[12];
    const float* at1 = (const float*)d_in[13]; const float* bo1 = (const float*)d_in[14];
    const float* Wl2 = (const float*)d_in[15]; const float* bl2 = (const float*)d_in[16];
    const float* Wr2 = (const float*)d_in[17]; const float* br2 = (const float*)d_in[18];
    const float* at2 = (const float*)d_in[19]; const float* bo2 = (const float*)d_in[20];
    const float* fc1W = (const float*)d_in[21]; const float* fc1b = (const float*)d_in[22];
    const float* fc2W = (const float*)d_in[23]; const float* fc2b = (const float*)d_in[24];
    float* out = (float*)d_out;

    // CSR build (per launch; graph identical each call but no caching allowed)
    k_init   <<<(GG*HH + 255)/256, 256>>>();
    k_hist   <<<(EE + 255)/256, 256>>>(ei);
    k_scan   <<<1, 1024>>>();
    k_setcur <<<(NN + 255)/256, 256>>>();
    k_scatter<<<(EE + 255)/256, 256>>>(ei);

    // layer 0
    k_lin0<<<(NN + 31)/32, 128>>>(x, Wl0, bl0, Wr0, br0);
    k_edge<<<(NN + 7)/8, 256>>>(at0, bo0);
    // layer 1
    k_lin <<<(NN + 31)/32, 256>>>(Wl1, bl1, Wr1, br1);
    k_edge<<<(NN + 7)/8, 256>>>(at1, bo1);
    // layer 2
    k_lin <<<(NN + 31)/32, 256>>>(Wl2, bl2, Wr2, br2);
    k_edge<<<(NN + 7)/8, 256>>>(at2, bo2);

    // pool + head
    k_pool<<<(NN*32 + 255)/256, 256>>>(batch);
    k_head<<<GG, 128>>>(fc1W, fc1b, fc2W, fc2b, out);
}

// round 2
// speedup vs baseline: 1.2874x; 1.2874x over previous
#include <cuda_runtime.h>
#include <math.h>

#define NN 50000
#define EE 1600000
#define HIN 7
#define HH 128
#define FCC 256
#define CC 2
#define GG 512

// ---------------- scratch (device globals; no allocation in launch) ----------
__device__ float g_h [NN*HH];   // current node features (layer output)
__device__ float g_xl[NN*HH];   // source-transformed features
__device__ float g_xr[NN*HH];   // target-transformed features
__device__ int   g_off[NN+1];   // CSR offsets (by dst)
__device__ int   g_cur[NN];     // degree counts / scatter cursors
__device__ int   g_csrc[EE];    // CSR src indices
__device__ float g_pool[GG*HH]; // pooled sums
__device__ int   g_cnt[GG];     // nodes per graph

__device__ __forceinline__ float lrelu02(float x){ return x > 0.f ? x : 0.2f*x; }
__device__ __forceinline__ float eluf(float x){ return x > 0.f ? x : (__expf(x) - 1.f); }

// ---------------- CSR build --------------------------------------------------
__global__ void k_init() {
    int i = blockIdx.x*blockDim.x + threadIdx.x;
    if (i < NN)    g_cur[i]  = 0;
    if (i < GG*HH) g_pool[i] = 0.f;
    if (i < GG)    g_cnt[i]  = 0;
}

__global__ void k_hist(const int* __restrict__ ei) {
    int i = blockIdx.x*blockDim.x + threadIdx.x;
    if (i < EE) atomicAdd(&g_cur[ei[EE + i]], 1);
}

__global__ void k_scan() {
    __shared__ int sums[1024];
    const int t = threadIdx.x;
    const int PER = (NN + 1023) / 1024;   // 49
    int base = t * PER;
    int local = 0;
    for (int k = 0; k < PER; k++) { int i = base + k; if (i < NN) local += g_cur[i]; }
    sums[t] = local; __syncthreads();
    for (int d = 1; d < 1024; d <<= 1) {
        int v = (t >= d) ? sums[t - d] : 0;
        __syncthreads();
        sums[t] += v;
        __syncthreads();
    }
    int prefix = (t == 0) ? 0 : sums[t - 1];
    for (int k = 0; k < PER; k++) {
        int i = base + k;
        if (i < NN) { int d = g_cur[i]; g_off[i] = prefix; prefix += d; }
    }
    if (t == 1023) g_off[NN] = prefix;
}

__global__ void k_setcur() {
    int i = blockIdx.x*blockDim.x + threadIdx.x;
    if (i < NN) g_cur[i] = g_off[i];
}

__global__ void k_scatter(const int* __restrict__ ei) {
    int i = blockIdx.x*blockDim.x + threadIdx.x;
    if (i >= EE) return;
    int s = ei[i];
    int d = ei[EE + i];
    int pos = atomicAdd(&g_cur[d], 1);
    g_csrc[pos] = s;
}

// ---------------- layer 0 linear (K=7) ---------------------------------------
__global__ __launch_bounds__(128) void k_lin0(const float* __restrict__ x,
                                              const float* __restrict__ Wl, const float* __restrict__ bl,
                                              const float* __restrict__ Wr, const float* __restrict__ br) {
    __shared__ float xs[32*HIN];
    const int t = threadIdx.x;                // output column 0..127
    const int n0 = blockIdx.x * 32;
    for (int i = t; i < 32*HIN; i += 128) {
        int n = n0 + i / HIN;
        xs[i] = (n < NN) ? x[n*HIN + (i % HIN)] : 0.f;
    }
    __syncthreads();
    float wl[HIN], wr[HIN];
#pragma unroll
    for (int k = 0; k < HIN; k++) { wl[k] = Wl[k*HH + t]; wr[k] = Wr[k*HH + t]; }
    float blv = bl[t], brv = br[t];
    for (int nn = 0; nn < 32; nn++) {
        int n = n0 + nn;
        if (n >= NN) break;
        float al = blv, ar = brv;
#pragma unroll
        for (int k = 0; k < HIN; k++) {
            float xv = xs[nn*HIN + k];
            al += xv * wl[k];
            ar += xv * wr[k];
        }
        g_xl[n*HH + t] = al;
        g_xr[n*HH + t] = ar;
    }
}

// ---------------- dual linear (K=128): xl = h@Wl+bl ; xr = h@Wr+br -----------
// block: 32 rows x 256 cols (128 xl || 128 xr), 256 threads, 4x8 micro-tile
__global__ __launch_bounds__(256) void k_lin(const float* __restrict__ Wl, const float* __restrict__ bl,
                                             const float* __restrict__ Wr, const float* __restrict__ br) {
    __shared__ float As[32][68];     // [k][row], padded
    __shared__ float Ws[32*256];     // [k][col]
    const int t   = threadIdx.x;
    const int row0 = blockIdx.x * 32;
    const int tc = t & 31;           // 0..31
    const int tr = t >> 5;           // 0..7 -> rows 4*tr..4*tr+3
    float acc[4][8];
#pragma unroll
    for (int i = 0; i < 4; i++)
#pragma unroll
        for (int j = 0; j < 8; j++) acc[i][j] = 0.f;

    for (int kt = 0; kt < HH; kt += 32) {
        {   // A tile: 32 rows x 32 k, stored transposed
            int r  = t >> 3;          // 0..31
            int kq = t & 7;           // 0..7 -> k = 4*kq..4*kq+3
            int row = row0 + r;
            float4 v = make_float4(0.f, 0.f, 0.f, 0.f);
            if (row < NN) v = *(const float4*)(g_h + row*HH + kt + kq*4);
            As[kq*4+0][r] = v.x; As[kq*4+1][r] = v.y;
            As[kq*4+2][r] = v.z; As[kq*4+3][r] = v.w;
        }
#pragma unroll
        for (int q = 0; q < 8; q++) {  // W tile: 32 k x 256 cols
            int s  = t + 256*q;        // 0..2047 float4 slots
            int k  = s >> 6;
            int c4 = (s & 63) * 4;
            const float* src = (c4 < HH) ? (Wl + (kt + k)*HH + c4)
                                         : (Wr + (kt + k)*HH + (c4 - HH));
            *(float4*)(Ws + k*256 + c4) = *(const float4*)src;
        }
        __syncthreads();
#pragma unroll
        for (int k = 0; k < 32; k++) {
            float a0 = As[k][4*tr+0], a1 = As[k][4*tr+1];
            float a2 = As[k][4*tr+2], a3 = As[k][4*tr+3];
#pragma unroll
            for (int j = 0; j < 8; j++) {
                float b = Ws[k*256 + tc + 32*j];
                acc[0][j] += a0*b; acc[1][j] += a1*b;
                acc[2][j] += a2*b; acc[3][j] += a3*b;
            }
        }
        __syncthreads();
    }
#pragma unroll
    for (int i = 0; i < 4; i++) {
        int row = row0 + 4*tr + i;
        if (row >= NN) continue;
#pragma unroll
        for (int j = 0; j < 8; j++) {
            int c = tc + 32*j;
            if (c < HH) g_xl[row*HH + c]        = acc[i][j] + bl[c];
            else        g_xr[row*HH + (c - HH)] = acc[i][j] + br[c - HH];
        }
    }
}

// ---------------- fused edge attention + ONLINE softmax + aggregate ----------
// one warp per destination node; single pass over in-edges with accumulator
// rescaling (flash-attention style). Self-loop seeds the state.
__global__ __launch_bounds__(256) void k_edge(const float* __restrict__ att,
                                              const float* __restrict__ bo) {
    const int gw   = (blockIdx.x * 256 + threadIdx.x) >> 5;
    const int lane = threadIdx.x & 31;
    if (gw >= NN) return;
    const int dst = gw;

    const float4* __restrict__ xlv = (const float4*)g_xl;
    const float4* __restrict__ xrv = (const float4*)g_xr;

    float4 a4  = *(const float4*)(att + lane*4);
    float4 xr4 = xrv[dst*32 + lane];
    float4 xd4 = xlv[dst*32 + lane];   // xl[dst] for self-loop

    // self-loop logit
    float p = a4.x*lrelu02(xd4.x + xr4.x) + a4.y*lrelu02(xd4.y + xr4.y)
            + a4.z*lrelu02(xd4.z + xr4.z) + a4.w*lrelu02(xd4.w + xr4.w);
#pragma unroll
    for (int o = 16; o > 0; o >>= 1) p += __shfl_xor_sync(0xffffffffu, p, o);

    // online softmax state seeded with self-loop (weight exp(0)=1)
    float m = p, s = 1.0f;
    float4 acc = xd4;

    const int beg = g_off[dst], end = g_off[dst + 1];

    // software pipeline: prefetch next src row across the shuffle reduction
    int   sn_n = 0;
    float4 v_n = make_float4(0.f,0.f,0.f,0.f);
    if (beg < end) { sn_n = g_csrc[beg]; v_n = xlv[sn_n*32 + lane]; }

    for (int j = beg; j < end; j++) {
        float4 v = v_n;
        if (j + 1 < end) { sn_n = g_csrc[j+1]; v_n = xlv[sn_n*32 + lane]; }

        float q = a4.x*lrelu02(v.x + xr4.x) + a4.y*lrelu02(v.y + xr4.y)
                + a4.z*lrelu02(v.z + xr4.z) + a4.w*lrelu02(v.w + xr4.w);
#pragma unroll
        for (int o = 16; o > 0; o >>= 1) q += __shfl_xor_sync(0xffffffffu, q, o);

        if (q > m) {            // warp-uniform branch (q, m uniform)
            float r = __expf(m - q);
            s = s*r + 1.0f;
            acc.x = acc.x*r + v.x; acc.y = acc.y*r + v.y;
            acc.z = acc.z*r + v.z; acc.w = acc.w*r + v.w;
            m = q;
        } else {
            float w = __expf(q - m);
            s += w;
            acc.x += w*v.x; acc.y += w*v.y;
            acc.z += w*v.z; acc.w += w*v.w;
        }
    }

    const float inv = 1.0f / s;
    float4 b4 = *(const float4*)(bo + lane*4);
    float4 o;
    o.x = eluf(acc.x*inv + b4.x); o.y = eluf(acc.y*inv + b4.y);
    o.z = eluf(acc.z*inv + b4.z); o.w = eluf(acc.w*inv + b4.w);
    ((float4*)g_h)[dst*32 + lane] = o;
}

// ---------------- global mean pool (run-length compressed atomics) -----------
// batch[] is sorted, so each warp walks 32 consecutive nodes and only flushes
// to global atomics when the graph id changes.
__global__ __launch_bounds__(256) void k_pool(const int* __restrict__ batch) {
    const int warp = (blockIdx.x * 256 + threadIdx.x) >> 5;
    const int lane = threadIdx.x & 31;
    const int n0 = warp * 32;
    if (n0 >= NN) return;
    const int n1 = min(n0 + 32, NN);

    const float4* __restrict__ hv = (const float4*)g_h;

    int curg = -1, run = 0;
    float4 acc = make_float4(0.f,0.f,0.f,0.f);

    for (int node = n0; node < n1; node++) {
        int g = batch[node];
        if (g != curg) {
            if (run > 0) {
                atomicAdd(&g_pool[curg*HH + lane*4 + 0], acc.x);
                atomicAdd(&g_pool[curg*HH + lane*4 + 1], acc.y);
                atomicAdd(&g_pool[curg*HH + lane*4 + 2], acc.z);
                atomicAdd(&g_pool[curg*HH + lane*4 + 3], acc.w);
                if (lane == 0) atomicAdd(&g_cnt[curg], run);
            }
            curg = g; run = 0;
            acc = make_float4(0.f,0.f,0.f,0.f);
        }
        float4 v = hv[node*32 + lane];
        acc.x += v.x; acc.y += v.y; acc.z += v.z; acc.w += v.w;
        run++;
    }
    if (run > 0) {
        atomicAdd(&g_pool[curg*HH + lane*4 + 0], acc.x);
        atomicAdd(&g_pool[curg*HH + lane*4 + 1], acc.y);
        atomicAdd(&g_pool[curg*HH + lane*4 + 2], acc.z);
        atomicAdd(&g_pool[curg*HH + lane*4 + 3], acc.w);
        if (lane == 0) atomicAdd(&g_cnt[curg], run);
    }
}

// ---------------- MLP head + log_softmax -------------------------------------
__global__ __launch_bounds__(128) void k_head(const float* __restrict__ fc1W, const float* __restrict__ fc1b,
                                              const float* __restrict__ fc2W, const float* __restrict__ fc2b,
                                              float* __restrict__ out) {
    __shared__ float gs[HH];
    __shared__ float red0[128], red1[128];
    const int gid = blockIdx.x;
    const int t = threadIdx.x;
    float c = (float)g_cnt[gid];
    if (c < 1.f) c = 1.f;
    gs[t] = g_pool[gid*HH + t] / c;
    __syncthreads();
    float p0 = 0.f, p1 = 0.f;
    for (int cc = t; cc < FCC; cc += 128) {
        float z = fc1b[cc];
        for (int k = 0; k < HH; k++) z += gs[k] * fc1W[k*FCC + cc];
        z = fmaxf(z, 0.f);
        p0 += z * fc2W[cc*CC + 0];
        p1 += z * fc2W[cc*CC + 1];
    }
    red0[t] = p0; red1[t] = p1;
    __syncthreads();
    for (int st = 64; st > 0; st >>= 1) {
        if (t < st) { red0[t] += red0[t + st]; red1[t] += red1[t + st]; }
        __syncthreads();
    }
    if (t == 0) {
        float l0 = red0[0] + fc2b[0];
        float l1 = red1[0] + fc2b[1];
        float mm  = fmaxf(l0, l1);
        float lse = mm + logf(__expf(l0 - mm) + __expf(l1 - mm));
        out[gid*CC + 0] = l0 - lse;
        out[gid*CC + 1] = l1 - lse;
    }
}

// ---------------- launch ------------------------------------------------------
extern "C" void kernel_launch(void* const* d_in, const int* in_sizes, int n_in,
                              void* d_out, int out_size) {
    const float* x     = (const float*)d_in[0];
    const int*   ei    = (const int*)  d_in[1];
    const int*   batch = (const int*)  d_in[2];
    const float* Wl0 = (const float*)d_in[3];  const float* bl0 = (const float*)d_in[4];
    const float* Wr0 = (const float*)d_in[5];  const float* br0 = (const float*)d_in[6];
    const float* at0 = (const float*)d_in[7];  const float* bo0 = (const float*)d_in[8];
    const float* Wl1 = (const float*)d_in[9];  const float* bl1 = (const float*)d_in[10];
    const float* Wr1 = (const float*)d_in[11]; const float* br1 = (const float*)d_in[12];
    const float* at1 = (const float*)d_in[13]; const float* bo1 = (const float*)d_in[14];
    const float* Wl2 = (const float*)d_in[15]; const float* bl2 = (const float*)d_in[16];
    const float* Wr2 = (const float*)d_in[17]; const float* br2 = (const float*)d_in[18];
    const float* at2 = (const float*)d_in[19]; const float* bo2 = (const float*)d_in[20];
    const float* fc1W = (const float*)d_in[21]; const float* fc1b = (const float*)d_in[22];
    const float* fc2W = (const float*)d_in[23]; const float* fc2b = (const float*)d_in[24];
    float* out = (float*)d_out;

    // CSR build (per launch; graph identical each call but no caching allowed)
    k_init   <<<(GG*HH + 255)/256, 256>>>();
    k_hist   <<<(EE + 255)/256, 256>>>(ei);
    k_scan   <<<1, 1024>>>();
    k_setcur <<<(NN + 255)/256, 256>>>();
    k_scatter<<<(EE + 255)/256, 256>>>(ei);

    // layer 0
    k_lin0<<<(NN + 31)/32, 128>>>(x, Wl0, bl0, Wr0, br0);
    k_edge<<<(NN + 7)/8, 256>>>(at0, bo0);
    // layer 1
    k_lin <<<(NN + 31)/32, 256>>>(Wl1, bl1, Wr1, br1);
    k_edge<<<(NN + 7)/8, 256>>>(at1, bo1);
    // layer 2
    k_lin <<<(NN + 31)/32, 256>>>(Wl2, bl2, Wr2, br2);
    k_edge<<<(NN + 7)/8, 256>>>(at2, bo2);

    // pool + head
    k_pool<<<(NN + 7)/8, 256>>>(batch);
    k_head<<<GG, 128>>>(fc1W, fc1b, fc2W, fc2b, out);
}